// round 15
// baseline (speedup 1.0000x reference)
#include <cuda_runtime.h>
#include <cuda_fp16.h>
#include <cstdint>

#define B_ 2
#define T_ 2048
#define C_ 1024
#define H_ 16
#define D_ 64
#define M_ (B_*T_)
#define N3_ (3*C_)

// Scratch (fp16 values): Q (pre-scaled by 1/8), K in [b,h,t,d]; V^T in [b,h,d,t].
__device__ __half g_q [B_*H_*T_*D_];
__device__ __half g_k [B_*H_*T_*D_];
__device__ __half g_vt[B_*H_*D_*T_];
// fp16 copies of x and W
__device__ __half g_x [M_*C_];
__device__ __half g_w [N3_*C_];

// ---------------------------------------------------------------------------
// helpers (base sm_80 PTX)
// ---------------------------------------------------------------------------
__device__ __forceinline__ uint32_t smem_u32(const void* p){
    uint32_t a;
    asm("{ .reg .u64 t; cvta.to.shared.u64 t, %1; cvt.u32.u64 %0, t; }" : "=r"(a) : "l"(p));
    return a;
}
__device__ __forceinline__ uint32_t pack2(float x, float y){
    __half2 h = __floats2half2_rn(x, y);
    return *(uint32_t*)&h;
}
__device__ __forceinline__ uint32_t relu2(uint32_t v){
    uint32_t r;
    asm("max.f16x2 %0, %1, %2;" : "=r"(r) : "r"(v), "r"(0u));
    return r;
}
__device__ __forceinline__ void ldsm4(uint32_t (&r)[4], uint32_t a){
    asm volatile("ldmatrix.sync.aligned.m8n8.x4.shared.b16 {%0,%1,%2,%3}, [%4];"
        : "=r"(r[0]), "=r"(r[1]), "=r"(r[2]), "=r"(r[3]) : "r"(a));
}
__device__ __forceinline__ void mma16(float (&d)[4], uint32_t a0, uint32_t a1, uint32_t a2, uint32_t a3,
                                      uint32_t b0, uint32_t b1){
    asm volatile("mma.sync.aligned.m16n8k16.row.col.f32.f16.f16.f32 "
        "{%0,%1,%2,%3}, {%4,%5,%6,%7}, {%8,%9}, {%0,%1,%2,%3};"
        : "+f"(d[0]), "+f"(d[1]), "+f"(d[2]), "+f"(d[3])
        : "r"(a0), "r"(a1), "r"(a2), "r"(a3), "r"(b0), "r"(b1));
}
__device__ __forceinline__ void cp16(uint32_t dst, const void* src){
    asm volatile("cp.async.cg.shared.global [%0], [%1], 16;" :: "r"(dst), "l"(src) : "memory");
}
__device__ __forceinline__ void cp_commit(){ asm volatile("cp.async.commit_group;" ::: "memory"); }
__device__ __forceinline__ void cp_wait0(){ asm volatile("cp.async.wait_group 0;" ::: "memory"); }
__device__ __forceinline__ void cp_wait1(){ asm volatile("cp.async.wait_group 1;" ::: "memory"); }

// ---------------------------------------------------------------------------
// Kernel 0: fp16-convert x and W into g_x, g_w (8 floats -> 8 halves / thread).
// ---------------------------------------------------------------------------
#define NX8_ (M_*C_/8)
#define NW8_ (N3_*C_/8)
__global__ __launch_bounds__(256) void round_kernel(
    const float* __restrict__ x, const float* __restrict__ W)
{
    const int i = blockIdx.x * 256 + threadIdx.x;
    const float4* src; __half* dst;
    if (i < NX8_)              { src = (const float4*)x + (size_t)i * 2;          dst = g_x + (size_t)i * 8; }
    else if (i < NX8_ + NW8_)  { const int j = i - NX8_;
                                 src = (const float4*)W + (size_t)j * 2;          dst = g_w + (size_t)j * 8; }
    else return;
    float4 v0 = __ldg(src), v1 = __ldg(src + 1);
    uint4 o;
    o.x = pack2(v0.x, v0.y); o.y = pack2(v0.z, v0.w);
    o.z = pack2(v1.x, v1.y); o.w = pack2(v1.z, v1.w);
    *(uint4*)dst = o;
}

// ---------------------------------------------------------------------------
// Kernel 1: QKV = g_x @ g_w^T + b  (M=4096, N=3072, K=1024), fp16 m16n8k16.
// 128x128 CTA tile, 256 threads, BK=64, 3-stage cp.async, 2 CTAs/SM.
// Q stored PRE-SCALED by 1/8. (R14 config — unchanged.)
// ---------------------------------------------------------------------------
__global__ void __launch_bounds__(256, 2) qkv_mma_kernel(const float* __restrict__ bias)
{
    extern __shared__ __align__(1024) char smem[];
    const uint32_t s0 = smem_u32(smem);
    const int tid = threadIdx.x, lane = tid & 31, wid = tid >> 5;
    const int wm = wid >> 2, wn = wid & 3;
    const int m0 = blockIdx.y * 128, n0 = blockIdx.x * 128;

    const int lrow = (lane & 7) + ((lane >> 3) & 1) * 8;
    const int lhi  = lane >> 4;

    auto loadAB = [&](int kt, int st) {
        const uint32_t Ab = s0 + st * 32768, Bb = Ab + 16384;
        #pragma unroll
        for (int i = 0; i < 4; i++) {
            const int s = tid + 256 * i, row = s >> 3, c = s & 7;
            const uint32_t off = row * 128 + ((c ^ (row & 7)) << 4);
            cp16(Ab + off, g_x + (size_t)(m0 + row) * C_ + kt * 64 + c * 8);
            cp16(Bb + off, g_w + (size_t)(n0 + row) * C_ + kt * 64 + c * 8);
        }
    };

    float acc[4][4][4] = {};

    loadAB(0, 0); cp_commit();
    loadAB(1, 1); cp_commit();

    for (int kt = 0; kt < 16; kt++) {
        if (kt < 15) cp_wait1(); else cp_wait0();
        __syncthreads();
        if (kt + 2 < 16) { loadAB(kt + 2, (kt + 2) % 3); cp_commit(); }

        const uint32_t Ab = s0 + (kt % 3) * 32768, Bb = Ab + 16384;
        #pragma unroll
        for (int kk = 0; kk < 4; kk++) {
            uint32_t a[4][4], bm[2][4];
            #pragma unroll
            for (int mi = 0; mi < 4; mi++)
                ldsm4(a[mi], Ab + (wm*64 + mi*16 + lrow) * 128 + (((kk*2 + lhi) ^ (lrow & 7)) << 4));
            #pragma unroll
            for (int pr = 0; pr < 2; pr++)
                ldsm4(bm[pr], Bb + (wn*32 + pr*16 + lrow) * 128 + (((kk*2 + lhi) ^ (lrow & 7)) << 4));
            #pragma unroll
            for (int mi = 0; mi < 4; mi++)
                #pragma unroll
                for (int ni = 0; ni < 4; ni++)
                    mma16(acc[mi][ni], a[mi][0], a[mi][1], a[mi][2], a[mi][3],
                          bm[ni>>1][ni & 1], bm[ni>>1][2 + (ni & 1)]);
        }
    }
    __syncthreads();

    const int part = n0 >> 10;
    if (part < 2) {
        const float qscale = (part == 0) ? 0.125f : 1.0f;
        #pragma unroll
        for (int mi = 0; mi < 4; mi++) {
            #pragma unroll
            for (int half = 0; half < 2; half++) {
                const int m = m0 + wm*64 + mi*16 + (lane >> 2) + half*8;
                const int bb = m >> 11, t = m & 2047;
                #pragma unroll
                for (int ni = 0; ni < 4; ni++) {
                    const int n = n0 + wn*32 + ni*8 + 2*(lane & 3);
                    const int hh = (n >> 6) & 15, d = n & 63;
                    const uint32_t hv = pack2((acc[mi][ni][half*2+0] + __ldg(bias + n)) * qscale,
                                              (acc[mi][ni][half*2+1] + __ldg(bias + n + 1)) * qscale);
                    __half* dst = (part == 0 ? g_q : g_k) + (((size_t)(bb*H_ + hh) * T_ + t) * D_ + d);
                    *(uint32_t*)dst = hv;
                }
            }
        }
    } else {
        __half* sv = (__half*)smem;
        #pragma unroll
        for (int mi = 0; mi < 4; mi++) {
            #pragma unroll
            for (int half = 0; half < 2; half++) {
                const int ml = wm*64 + mi*16 + (lane >> 2) + half*8;
                #pragma unroll
                for (int ni = 0; ni < 4; ni++) {
                    const int nl = wn*32 + ni*8 + 2*(lane & 3);
                    const int n = n0 + nl;
                    sv[(nl    ) * 144 + ml] = __float2half_rn(acc[mi][ni][half*2+0] + __ldg(bias + n));
                    sv[(nl + 1) * 144 + ml] = __float2half_rn(acc[mi][ni][half*2+1] + __ldg(bias + n + 1));
                }
            }
        }
        __syncthreads();
        const int hh = (n0 & 1023) >> 6;
        const int bb = m0 >> 11, t0 = m0 & 2047;
        #pragma unroll
        for (int i = 0; i < 8; i++) {
            const int idx = tid + 256 * i;
            const int row = idx >> 4, ch = idx & 15;
            uint4 v = *(const uint4*)(sv + row * 144 + ch * 8);
            const int h = hh + (row >> 6), d = row & 63;
            *(uint4*)(g_vt + ((size_t)(bb*H_ + h) * D_ + d) * T_ + t0 + ch * 8) = v;
        }
    }
}

// ---------------------------------------------------------------------------
// Kernel 2: Y = relu(Q' K^T, causal) @ V — Q pre-scaled; S in registers.
// 8 warps x 16 query rows, 128 keys per warp. 3-stage KV pipeline (Q smem
// region reused as 3rd stage after fragment hoist). h1 epilogue FUSED into
// its mma2 loop (4-reg transient S frags). 2 CTAs/SM. Global LPT.
// ---------------------------------------------------------------------------
__global__ void __launch_bounds__(256, 2) attn_mma_kernel(float* __restrict__ out)
{
    extern __shared__ __align__(1024) char smem[];
    const uint32_t s0 = smem_u32(smem);
    const uint32_t Qs = s0;                                // 16KB, dead after hoist
    // stage st: K at s0+16384+st*32768 (16KB), V at +16384 more. Total 112KB.

    const int tid = threadIdx.x, lane = tid & 31, wid = tid >> 5;
    const int gi = (int)blockIdx.x;                        // 0..511, global LPT
    const int qt = (T_/128 - 1) - (gi >> 5);               // all qt=15 first
    const int hb = gi & 31;
    const int h = hb & 15, bb = hb >> 4;
    const int q0 = qt * 128;
    const size_t bh = (size_t)(bb * H_ + h);
    const __half* Qg  = g_q  + bh * T_ * D_;
    const __half* Kg  = g_k  + bh * T_ * D_;
    const __half* Vtg = g_vt + bh * (size_t)D_ * T_;

    const int lrow = (lane & 7) + ((lane >> 3) & 1) * 8;
    const int lhi  = lane >> 4;

    auto Kst = [&](int st){ return s0 + 16384 + st * 32768; };
    auto Vst = [&](int st){ return s0 + 32768 + st * 32768; };

    auto loadKV = [&](int jt, int st) {
        const int j0 = jt * 128;
        #pragma unroll
        for (int i = 0; i < 4; i++) {
            int s = tid + 256 * i, row = s >> 3, c = s & 7;
            cp16(Kst(st) + row * 128 + ((c ^ (row & 7)) << 4),
                 Kg + (size_t)(j0 + row) * D_ + c * 8);
        }
        #pragma unroll
        for (int i = 0; i < 4; i++) {
            int s = tid + 256 * i, row = s >> 4, c = s & 15;
            cp16(Vst(st) + row * 256 + ((c ^ (row & 7)) << 4),
                 Vtg + (size_t)row * T_ + j0 + c * 8);
        }
    };

    // Prologue: g0 = Q + KV(0); g1 = KV(1) if it exists.
    #pragma unroll
    for (int i = 0; i < 4; i++) {
        int s = tid + 256 * i, row = s >> 3, c = s & 7;
        cp16(Qs + row * 128 + ((c ^ (row & 7)) << 4),
             Qg + (size_t)(q0 + row) * D_ + c * 8);
    }
    loadKV(0, 0);
    cp_commit();
    if (qt >= 1) { loadKV(1, 1); cp_commit(); }
    if (qt >= 1) cp_wait1(); else cp_wait0();   // g0 done
    __syncthreads();

    // Hoisted loop-invariant Q fragments (16 regs). Qs region dead after this.
    uint32_t qa[4][4];
    #pragma unroll
    for (int kk = 0; kk < 4; kk++)
        ldsm4(qa[kk], Qs + (wid*16 + lrow) * 128 + (((kk*2 + lhi) ^ (lrow & 7)) << 4));

    float accY[8][4] = {};
    const int r0 = q0 + wid*16 + (lane >> 2);

    float accS[8][4];
    uint32_t sf0[4][4];

    auto mma1 = [&](int p, int hf) {
        #pragma unroll
        for (int ni = 0; ni < 8; ni++)
            #pragma unroll
            for (int e = 0; e < 4; e++) accS[ni][e] = 0.f;
        #pragma unroll
        for (int kk = 0; kk < 4; kk++) {
            uint32_t bm[4][4];
            #pragma unroll
            for (int pr = 0; pr < 4; pr++)
                ldsm4(bm[pr], Kst(p) + (hf*64 + pr*16 + lrow) * 128 + (((kk*2 + lhi) ^ (lrow & 7)) << 4));
            #pragma unroll
            for (int ni = 0; ni < 8; ni++)
                mma16(accS[ni], qa[kk][0], qa[kk][1], qa[kk][2], qa[kk][3],
                      bm[ni>>1][ni & 1], bm[ni>>1][2 + (ni & 1)]);
        }
    };

    auto epi_clean = [&](uint32_t (&sf)[4][4]) {
        #pragma unroll
        for (int kk = 0; kk < 4; kk++) {
            #pragma unroll
            for (int half = 0; half < 2; half++) {
                const int ni = kk*2 + half;
                sf[kk][half*2 + 0] = relu2(pack2(accS[ni][0], accS[ni][1]));
                sf[kk][half*2 + 1] = relu2(pack2(accS[ni][2], accS[ni][3]));
            }
        }
    };

    auto epi_diag = [&](int j0, int hf, uint32_t (&sf)[4][4]) {
        #pragma unroll
        for (int kk = 0; kk < 4; kk++) {
            #pragma unroll
            for (int half = 0; half < 2; half++) {
                const int ni = kk*2 + half;
                float v0 = accS[ni][0], v1 = accS[ni][1];
                float v2 = accS[ni][2], v3 = accS[ni][3];
                const int k0 = j0 + hf*64 + ni*8 + 2*(lane & 3);
                v0 = (v0 > 0.f && k0     <= r0    ) ? v0 : 0.f;
                v1 = (v1 > 0.f && k0 + 1 <= r0    ) ? v1 : 0.f;
                v2 = (v2 > 0.f && k0     <= r0 + 8) ? v2 : 0.f;
                v3 = (v3 > 0.f && k0 + 1 <= r0 + 8) ? v3 : 0.f;
                sf[kk][half*2 + 0] = pack2(v0, v1);
                sf[kk][half*2 + 1] = pack2(v2, v3);
            }
        }
    };

    auto mma2 = [&](int p, int hf, const uint32_t (&sf)[4][4]) {
        #pragma unroll
        for (int kk = 0; kk < 4; kk++) {
            uint32_t bm[4][4];
            #pragma unroll
            for (int pr = 0; pr < 4; pr++)
                ldsm4(bm[pr], Vst(p) + (pr*16 + lrow) * 256 + (((hf*8 + kk*2 + lhi) ^ (lrow & 7)) << 4));
            #pragma unroll
            for (int ni = 0; ni < 8; ni++)
                mma16(accY[ni], sf[kk][0], sf[kk][1], sf[kk][2], sf[kk][3],
                      bm[ni>>1][ni & 1], bm[ni>>1][2 + (ni & 1)]);
        }
    };

    // h1 epilogue fused into its mma2: per-kk 4-reg transient S fragment.
    auto mma2_fused = [&](int p, int hf, bool msk, int j0) {
        #pragma unroll
        for (int kk = 0; kk < 4; kk++) {
            uint32_t sfv[4];
            if (msk) {
                #pragma unroll
                for (int half = 0; half < 2; half++) {
                    const int ni = kk*2 + half;
                    float v0 = accS[ni][0], v1 = accS[ni][1];
                    float v2 = accS[ni][2], v3 = accS[ni][3];
                    const int k0 = j0 + hf*64 + ni*8 + 2*(lane & 3);
                    v0 = (v0 > 0.f && k0     <= r0    ) ? v0 : 0.f;
                    v1 = (v1 > 0.f && k0 + 1 <= r0    ) ? v1 : 0.f;
                    v2 = (v2 > 0.f && k0     <= r0 + 8) ? v2 : 0.f;
                    v3 = (v3 > 0.f && k0 + 1 <= r0 + 8) ? v3 : 0.f;
                    sfv[half*2 + 0] = pack2(v0, v1);
                    sfv[half*2 + 1] = pack2(v2, v3);
                }
            } else {
                sfv[0] = relu2(pack2(accS[kk*2  ][0], accS[kk*2  ][1]));
                sfv[1] = relu2(pack2(accS[kk*2  ][2], accS[kk*2  ][3]));
                sfv[2] = relu2(pack2(accS[kk*2+1][0], accS[kk*2+1][1]));
                sfv[3] = relu2(pack2(accS[kk*2+1][2], accS[kk*2+1][3]));
            }
            uint32_t bm[4][4];
            #pragma unroll
            for (int pr = 0; pr < 4; pr++)
                ldsm4(bm[pr], Vst(p) + (pr*16 + lrow) * 256 + (((hf*8 + kk*2 + lhi) ^ (lrow & 7)) << 4));
            #pragma unroll
            for (int ni = 0; ni < 8; ni++)
                mma16(accY[ni], sfv[0], sfv[1], sfv[2], sfv[3],
                      bm[ni>>1][ni & 1], bm[ni>>1][2 + (ni & 1)]);
        }
    };

    for (int jt = 0; jt <= qt; jt++) {
        const int p = jt % 3;
        const int j0 = jt * 128;
        if (jt > 0) {
            if (jt < qt) cp_wait1(); else cp_wait0();
            __syncthreads();
        }
        if (jt + 2 <= qt) { loadKV(jt + 2, (jt + 2) % 3); cp_commit(); }

        const bool diag = (jt == qt);
        const bool doH1 = !(diag && wid < 4);

        mma1(p, 0);
        if (diag) epi_diag(j0, 0, sf0); else epi_clean(sf0);
        if (doH1) { mma1(p, 1); }
        mma2(p, 0, sf0);
        if (doH1) mma2_fused(p, 1, diag, j0);
    }

    // Epilogue: direct store.
    #pragma unroll
    for (int half = 0; half < 2; half++) {
        const int t = r0 - q0 + half*8 + q0;
        float* orow = out + ((size_t)bb * T_ + t) * C_ + h * D_;
        #pragma unroll
        for (int ni = 0; ni < 8; ni++) {
            const int d = ni*8 + 2*(lane & 3);
            *(float2*)(orow + d) = make_float2(accY[ni][half*2+0], accY[ni][half*2+1]);
        }
    }
}

extern "C" void kernel_launch(void* const* d_in, const int* in_sizes, int n_in,
                              void* d_out, int out_size)
{
    const float* x    = (const float*)d_in[0];
    const float* W    = (const float*)d_in[1];
    const float* bias = (const float*)d_in[2];
    float* out = (float*)d_out;

    const int qkv_smem  = 98304;    // 3 x 32KB stages
    const int attn_smem = 114688;   // Q16K + 3 x (K16K + V16K); 2 CTAs/SM (224K/SM)
    cudaFuncSetAttribute(qkv_mma_kernel,  cudaFuncAttributeMaxDynamicSharedMemorySize, qkv_smem);
    cudaFuncSetAttribute(attn_mma_kernel, cudaFuncAttributeMaxDynamicSharedMemorySize, attn_smem);

    round_kernel<<<(NX8_ + NW8_ + 255) / 256, 256>>>(x, W);

    dim3 g1(24, 32);                // N/128 x M/128
    qkv_mma_kernel<<<g1, 256, qkv_smem>>>(bias);

    attn_mma_kernel<<<512, 256, attn_smem>>>(out);
}

// round 16
// speedup vs baseline: 1.0360x; 1.0360x over previous
#include <cuda_runtime.h>
#include <cuda_fp16.h>
#include <cstdint>

#define B_ 2
#define T_ 2048
#define C_ 1024
#define H_ 16
#define D_ 64
#define M_ (B_*T_)
#define N3_ (3*C_)

// Scratch (fp16 values): Q (pre-scaled by 1/8), K in [b,h,t,d]; V^T in [b,h,d,t].
__device__ __half g_q [B_*H_*T_*D_];
__device__ __half g_k [B_*H_*T_*D_];
__device__ __half g_vt[B_*H_*D_*T_];
// fp16 copies of x and W
__device__ __half g_x [M_*C_];
__device__ __half g_w [N3_*C_];

// ---------------------------------------------------------------------------
// helpers (base sm_80 PTX)
// ---------------------------------------------------------------------------
__device__ __forceinline__ uint32_t smem_u32(const void* p){
    uint32_t a;
    asm("{ .reg .u64 t; cvta.to.shared.u64 t, %1; cvt.u32.u64 %0, t; }" : "=r"(a) : "l"(p));
    return a;
}
__device__ __forceinline__ uint32_t pack2(float x, float y){
    __half2 h = __floats2half2_rn(x, y);
    return *(uint32_t*)&h;
}
__device__ __forceinline__ uint32_t relu2(uint32_t v){
    uint32_t r;
    asm("max.f16x2 %0, %1, %2;" : "=r"(r) : "r"(v), "r"(0u));
    return r;
}
__device__ __forceinline__ void ldsm4(uint32_t (&r)[4], uint32_t a){
    asm volatile("ldmatrix.sync.aligned.m8n8.x4.shared.b16 {%0,%1,%2,%3}, [%4];"
        : "=r"(r[0]), "=r"(r[1]), "=r"(r[2]), "=r"(r[3]) : "r"(a));
}
__device__ __forceinline__ void mma16(float (&d)[4], uint32_t a0, uint32_t a1, uint32_t a2, uint32_t a3,
                                      uint32_t b0, uint32_t b1){
    asm volatile("mma.sync.aligned.m16n8k16.row.col.f32.f16.f16.f32 "
        "{%0,%1,%2,%3}, {%4,%5,%6,%7}, {%8,%9}, {%0,%1,%2,%3};"
        : "+f"(d[0]), "+f"(d[1]), "+f"(d[2]), "+f"(d[3])
        : "r"(a0), "r"(a1), "r"(a2), "r"(a3), "r"(b0), "r"(b1));
}
__device__ __forceinline__ void cp16(uint32_t dst, const void* src){
    asm volatile("cp.async.cg.shared.global [%0], [%1], 16;" :: "r"(dst), "l"(src) : "memory");
}
__device__ __forceinline__ void cp_commit(){ asm volatile("cp.async.commit_group;" ::: "memory"); }
__device__ __forceinline__ void cp_wait0(){ asm volatile("cp.async.wait_group 0;" ::: "memory"); }
__device__ __forceinline__ void cp_wait1(){ asm volatile("cp.async.wait_group 1;" ::: "memory"); }

// ---------------------------------------------------------------------------
// Kernel 0: fp16-convert x and W into g_x, g_w (8 floats -> 8 halves / thread).
// ---------------------------------------------------------------------------
#define NX8_ (M_*C_/8)
#define NW8_ (N3_*C_/8)
__global__ __launch_bounds__(256) void round_kernel(
    const float* __restrict__ x, const float* __restrict__ W)
{
    const int i = blockIdx.x * 256 + threadIdx.x;
    const float4* src; __half* dst;
    if (i < NX8_)              { src = (const float4*)x + (size_t)i * 2;          dst = g_x + (size_t)i * 8; }
    else if (i < NX8_ + NW8_)  { const int j = i - NX8_;
                                 src = (const float4*)W + (size_t)j * 2;          dst = g_w + (size_t)j * 8; }
    else return;
    float4 v0 = __ldg(src), v1 = __ldg(src + 1);
    uint4 o;
    o.x = pack2(v0.x, v0.y); o.y = pack2(v0.z, v0.w);
    o.z = pack2(v1.x, v1.y); o.w = pack2(v1.z, v1.w);
    *(uint4*)dst = o;
}

// ---------------------------------------------------------------------------
// Kernel 1: QKV = g_x @ g_w^T + b  (M=4096, N=3072, K=1024), fp16 m16n8k16.
// 128x128 CTA tile, 256 threads, BK=64, 3-stage cp.async, 2 CTAs/SM.
// Q stored PRE-SCALED by 1/8. Bias hoisted to registers in epilogue.
// ---------------------------------------------------------------------------
__global__ void __launch_bounds__(256, 2) qkv_mma_kernel(const float* __restrict__ bias)
{
    extern __shared__ __align__(1024) char smem[];
    const uint32_t s0 = smem_u32(smem);
    const int tid = threadIdx.x, lane = tid & 31, wid = tid >> 5;
    const int wm = wid >> 2, wn = wid & 3;
    const int m0 = blockIdx.y * 128, n0 = blockIdx.x * 128;

    const int lrow = (lane & 7) + ((lane >> 3) & 1) * 8;
    const int lhi  = lane >> 4;

    auto loadAB = [&](int kt, int st) {
        const uint32_t Ab = s0 + st * 32768, Bb = Ab + 16384;
        #pragma unroll
        for (int i = 0; i < 4; i++) {
            const int s = tid + 256 * i, row = s >> 3, c = s & 7;
            const uint32_t off = row * 128 + ((c ^ (row & 7)) << 4);
            cp16(Ab + off, g_x + (size_t)(m0 + row) * C_ + kt * 64 + c * 8);
            cp16(Bb + off, g_w + (size_t)(n0 + row) * C_ + kt * 64 + c * 8);
        }
    };

    float acc[4][4][4] = {};

    loadAB(0, 0); cp_commit();
    loadAB(1, 1); cp_commit();

    for (int kt = 0; kt < 16; kt++) {
        if (kt < 15) cp_wait1(); else cp_wait0();
        __syncthreads();
        if (kt + 2 < 16) { loadAB(kt + 2, (kt + 2) % 3); cp_commit(); }

        const uint32_t Ab = s0 + (kt % 3) * 32768, Bb = Ab + 16384;
        #pragma unroll
        for (int kk = 0; kk < 4; kk++) {
            uint32_t a[4][4], bm[2][4];
            #pragma unroll
            for (int mi = 0; mi < 4; mi++)
                ldsm4(a[mi], Ab + (wm*64 + mi*16 + lrow) * 128 + (((kk*2 + lhi) ^ (lrow & 7)) << 4));
            #pragma unroll
            for (int pr = 0; pr < 2; pr++)
                ldsm4(bm[pr], Bb + (wn*32 + pr*16 + lrow) * 128 + (((kk*2 + lhi) ^ (lrow & 7)) << 4));
            #pragma unroll
            for (int mi = 0; mi < 4; mi++)
                #pragma unroll
                for (int ni = 0; ni < 4; ni++)
                    mma16(acc[mi][ni], a[mi][0], a[mi][1], a[mi][2], a[mi][3],
                          bm[ni>>1][ni & 1], bm[ni>>1][2 + (ni & 1)]);
        }
    }
    __syncthreads();

    // Bias hoist: 8 distinct per-thread column biases (ni x 2), loaded once.
    float bv[4][2];
    #pragma unroll
    for (int ni = 0; ni < 4; ni++) {
        const int n = n0 + wn*32 + ni*8 + 2*(lane & 3);
        bv[ni][0] = __ldg(bias + n);
        bv[ni][1] = __ldg(bias + n + 1);
    }

    const int part = n0 >> 10;
    if (part < 2) {
        const float qscale = (part == 0) ? 0.125f : 1.0f;
        #pragma unroll
        for (int mi = 0; mi < 4; mi++) {
            #pragma unroll
            for (int half = 0; half < 2; half++) {
                const int m = m0 + wm*64 + mi*16 + (lane >> 2) + half*8;
                const int bb = m >> 11, t = m & 2047;
                #pragma unroll
                for (int ni = 0; ni < 4; ni++) {
                    const int n = n0 + wn*32 + ni*8 + 2*(lane & 3);
                    const int hh = (n >> 6) & 15, d = n & 63;
                    const uint32_t hv = pack2((acc[mi][ni][half*2+0] + bv[ni][0]) * qscale,
                                              (acc[mi][ni][half*2+1] + bv[ni][1]) * qscale);
                    __half* dst = (part == 0 ? g_q : g_k) + (((size_t)(bb*H_ + hh) * T_ + t) * D_ + d);
                    *(uint32_t*)dst = hv;
                }
            }
        }
    } else {
        __half* sv = (__half*)smem;
        #pragma unroll
        for (int mi = 0; mi < 4; mi++) {
            #pragma unroll
            for (int half = 0; half < 2; half++) {
                const int ml = wm*64 + mi*16 + (lane >> 2) + half*8;
                #pragma unroll
                for (int ni = 0; ni < 4; ni++) {
                    const int nl = wn*32 + ni*8 + 2*(lane & 3);
                    sv[(nl    ) * 144 + ml] = __float2half_rn(acc[mi][ni][half*2+0] + bv[ni][0]);
                    sv[(nl + 1) * 144 + ml] = __float2half_rn(acc[mi][ni][half*2+1] + bv[ni][1]);
                }
            }
        }
        __syncthreads();
        const int hh = (n0 & 1023) >> 6;
        const int bb = m0 >> 11, t0 = m0 & 2047;
        #pragma unroll
        for (int i = 0; i < 8; i++) {
            const int idx = tid + 256 * i;
            const int row = idx >> 4, ch = idx & 15;
            uint4 v = *(const uint4*)(sv + row * 144 + ch * 8);
            const int h = hh + (row >> 6), d = row & 63;
            *(uint4*)(g_vt + ((size_t)(bb*H_ + h) * D_ + d) * T_ + t0 + ch * 8) = v;
        }
    }
}

// ---------------------------------------------------------------------------
// Kernel 2: Y = relu(Q' K^T, causal) @ V — Q pre-scaled; S in registers.
// 8 warps x 16 query rows, 128 keys per warp, halves interleaved (R14).
// Diagonal-tile h0 uses the cheap epilogue for warps 4-7 (provably unmasked).
// 2 CTAs/SM. Global LPT.
// ---------------------------------------------------------------------------
__global__ void __launch_bounds__(256, 2) attn_mma_kernel(float* __restrict__ out)
{
    extern __shared__ __align__(1024) char smem[];
    const uint32_t s0 = smem_u32(smem);
    const uint32_t Qs = s0;                                // 16KB
    const uint32_t Kst[2] = { s0 + 16384, s0 + 49152 };    // 16KB each
    const uint32_t Vst[2] = { s0 + 32768, s0 + 65536 };    // 16KB each; total 80KB

    const int tid = threadIdx.x, lane = tid & 31, wid = tid >> 5;
    const int gi = (int)blockIdx.x;                        // 0..511, global LPT
    const int qt = (T_/128 - 1) - (gi >> 5);               // all qt=15 first
    const int hb = gi & 31;
    const int h = hb & 15, bb = hb >> 4;
    const int q0 = qt * 128;
    const size_t bh = (size_t)(bb * H_ + h);
    const __half* Qg  = g_q  + bh * T_ * D_;
    const __half* Kg  = g_k  + bh * T_ * D_;
    const __half* Vtg = g_vt + bh * (size_t)D_ * T_;

    const int lrow = (lane & 7) + ((lane >> 3) & 1) * 8;
    const int lhi  = lane >> 4;

    auto loadKV = [&](int jt, int st) {
        const int j0 = jt * 128;
        #pragma unroll
        for (int i = 0; i < 4; i++) {
            int s = tid + 256 * i, row = s >> 3, c = s & 7;
            cp16(Kst[st] + row * 128 + ((c ^ (row & 7)) << 4),
                 Kg + (size_t)(j0 + row) * D_ + c * 8);
        }
        #pragma unroll
        for (int i = 0; i < 4; i++) {
            int s = tid + 256 * i, row = s >> 4, c = s & 15;
            cp16(Vst[st] + row * 256 + ((c ^ (row & 7)) << 4),
                 Vtg + (size_t)row * T_ + j0 + c * 8);
        }
    };

    // Prologue: Q + KV(0).
    #pragma unroll
    for (int i = 0; i < 4; i++) {
        int s = tid + 256 * i, row = s >> 3, c = s & 7;
        cp16(Qs + row * 128 + ((c ^ (row & 7)) << 4),
             Qg + (size_t)(q0 + row) * D_ + c * 8);
    }
    loadKV(0, 0);
    cp_commit();
    cp_wait0();
    __syncthreads();

    // Hoisted loop-invariant Q fragments (16 regs).
    uint32_t qa[4][4];
    #pragma unroll
    for (int kk = 0; kk < 4; kk++)
        ldsm4(qa[kk], Qs + (wid*16 + lrow) * 128 + (((kk*2 + lhi) ^ (lrow & 7)) << 4));

    float accY[8][4] = {};
    const int r0 = q0 + wid*16 + (lane >> 2);

    float accS[8][4];
    uint32_t sf0[4][4], sf1[4][4];

    auto mma1 = [&](int p, int hf) {
        #pragma unroll
        for (int ni = 0; ni < 8; ni++)
            #pragma unroll
            for (int e = 0; e < 4; e++) accS[ni][e] = 0.f;
        #pragma unroll
        for (int kk = 0; kk < 4; kk++) {
            uint32_t bm[4][4];
            #pragma unroll
            for (int pr = 0; pr < 4; pr++)
                ldsm4(bm[pr], Kst[p] + (hf*64 + pr*16 + lrow) * 128 + (((kk*2 + lhi) ^ (lrow & 7)) << 4));
            #pragma unroll
            for (int ni = 0; ni < 8; ni++)
                mma16(accS[ni], qa[kk][0], qa[kk][1], qa[kk][2], qa[kk][3],
                      bm[ni>>1][ni & 1], bm[ni>>1][2 + (ni & 1)]);
        }
    };

    auto epi_clean = [&](uint32_t (&sf)[4][4]) {
        #pragma unroll
        for (int kk = 0; kk < 4; kk++) {
            #pragma unroll
            for (int half = 0; half < 2; half++) {
                const int ni = kk*2 + half;
                sf[kk][half*2 + 0] = relu2(pack2(accS[ni][0], accS[ni][1]));
                sf[kk][half*2 + 1] = relu2(pack2(accS[ni][2], accS[ni][3]));
            }
        }
    };

    auto epi_diag = [&](int j0, int hf, uint32_t (&sf)[4][4]) {
        #pragma unroll
        for (int kk = 0; kk < 4; kk++) {
            #pragma unroll
            for (int half = 0; half < 2; half++) {
                const int ni = kk*2 + half;
                float v0 = accS[ni][0], v1 = accS[ni][1];
                float v2 = accS[ni][2], v3 = accS[ni][3];
                const int k0 = j0 + hf*64 + ni*8 + 2*(lane & 3);
                v0 = (v0 > 0.f && k0     <= r0    ) ? v0 : 0.f;
                v1 = (v1 > 0.f && k0 + 1 <= r0    ) ? v1 : 0.f;
                v2 = (v2 > 0.f && k0     <= r0 + 8) ? v2 : 0.f;
                v3 = (v3 > 0.f && k0 + 1 <= r0 + 8) ? v3 : 0.f;
                sf[kk][half*2 + 0] = pack2(v0, v1);
                sf[kk][half*2 + 1] = pack2(v2, v3);
            }
        }
    };

    auto mma2 = [&](int p, int hf, const uint32_t (&sf)[4][4]) {
        #pragma unroll
        for (int kk = 0; kk < 4; kk++) {
            uint32_t bm[4][4];
            #pragma unroll
            for (int pr = 0; pr < 4; pr++)
                ldsm4(bm[pr], Vst[p] + (pr*16 + lrow) * 256 + (((hf*8 + kk*2 + lhi) ^ (lrow & 7)) << 4));
            #pragma unroll
            for (int ni = 0; ni < 8; ni++)
                mma16(accY[ni], sf[kk][0], sf[kk][1], sf[kk][2], sf[kk][3],
                      bm[ni>>1][ni & 1], bm[ni>>1][2 + (ni & 1)]);
        }
    };

    for (int jt = 0; jt <= qt; jt++) {
        const int p = jt & 1;
        const int j0 = jt * 128;
        if (jt > 0) { cp_wait0(); __syncthreads(); }
        if (jt < qt) { loadKV(jt + 1, 1 - p); cp_commit(); }

        const bool diag = (jt == qt);
        const bool doH1 = !(diag && wid < 4);
        // Diagonal h0: only warps 0-3 (rows < q0+64) can straddle h0's keys.
        const bool maskH0 = diag && (wid < 4);

        mma1(p, 0);
        if (maskH0) epi_diag(j0, 0, sf0); else epi_clean(sf0);
        if (doH1) { mma1(p, 1); }
        mma2(p, 0, sf0);
        if (doH1) {
            if (diag) epi_diag(j0, 1, sf1); else epi_clean(sf1);
            mma2(p, 1, sf1);
        }
    }

    // Epilogue: direct store.
    #pragma unroll
    for (int half = 0; half < 2; half++) {
        const int t = r0 - q0 + half*8 + q0;
        float* orow = out + ((size_t)bb * T_ + t) * C_ + h * D_;
        #pragma unroll
        for (int ni = 0; ni < 8; ni++) {
            const int d = ni*8 + 2*(lane & 3);
            *(float2*)(orow + d) = make_float2(accY[ni][half*2+0], accY[ni][half*2+1]);
        }
    }
}

extern "C" void kernel_launch(void* const* d_in, const int* in_sizes, int n_in,
                              void* d_out, int out_size)
{
    const float* x    = (const float*)d_in[0];
    const float* W    = (const float*)d_in[1];
    const float* bias = (const float*)d_in[2];
    float* out = (float*)d_out;

    const int qkv_smem  = 98304;   // 3 x 32KB stages
    const int attn_smem = 81920;   // Q16K + 2 x (K16K + V16K); 2 CTAs/SM
    cudaFuncSetAttribute(qkv_mma_kernel,  cudaFuncAttributeMaxDynamicSharedMemorySize, qkv_smem);
    cudaFuncSetAttribute(attn_mma_kernel, cudaFuncAttributeMaxDynamicSharedMemorySize, attn_smem);

    round_kernel<<<(NX8_ + NW8_ + 255) / 256, 256>>>(x, W);

    dim3 g1(24, 32);               // N/128 x M/128
    qkv_mma_kernel<<<g1, 256, qkv_smem>>>(bias);

    attn_mma_kernel<<<512, 256, attn_smem>>>(out);
}